// round 14
// baseline (speedup 1.0000x reference)
#include <cuda_runtime.h>
#include <math.h>

#define BN 4096      // total nodes (B*N)
#define NN 1024      // nodes per graph
#define KK 128       // neighbours
#define DD 32        // feature dim
#define EH 130       // edge hidden
#define EHP 132      // padded edge hidden (mult of 4)

typedef unsigned long long u64;

__device__ float g_feats[2][BN*DD];
__device__ float g_coors[2][BN*2];
__device__ int   g_idx[BN*KK];
__device__ float g_dist[BN*KK];
__device__ float g_A[BN*EHP];
__device__ float g_Bv[BN*EHP];
__device__ float g_msum[BN*DD];

__device__ __forceinline__ float lrelu(float x){ return fmaxf(x, 0.1f*x); }

__device__ __forceinline__ u64 pk2(float lo, float hi){
    u64 r; asm("mov.b64 %0, {%1,%2};" : "=l"(r) : "f"(lo), "f"(hi)); return r;
}
__device__ __forceinline__ float2 upk2(u64 v){
    float2 f; asm("mov.b64 {%0,%1}, %2;" : "=f"(f.x), "=f"(f.y) : "l"(v)); return f;
}
__device__ __forceinline__ u64 fma2_(u64 a, u64 b, u64 c){
    u64 d; asm("fma.rn.f32x2 %0, %1, %2, %3;" : "=l"(d) : "l"(a), "l"(b), "l"(c)); return d;
}
__device__ __forceinline__ u64 add2_(u64 a, u64 b){
    u64 d; asm("add.rn.f32x2 %0, %1, %2;" : "=l"(d) : "l"(a), "l"(b)); return d;
}
__device__ __forceinline__ u64 mul2_(u64 a, u64 b){
    u64 d; asm("mul.rn.f32x2 %0, %1, %2;" : "=l"(d) : "l"(a), "l"(b)); return d;
}

// ================= knn body: exact top-128 via 10-bit radix select (512 thr, 2 keys/thr) =================
__device__ void knn_body(int gi, int cur){
    __shared__ float2 sc[NN];
    __shared__ unsigned int hist[1024];
    __shared__ u64 cand[NN];
    __shared__ unsigned int sWarp[16][2];
    __shared__ unsigned int sScan[16];
    __shared__ unsigned int sT, sNeed;

    int t = threadIdx.x;               // 512 threads
    int b = gi >> 10, il = gi & 1023;
    const float2* C = (const float2*)(g_coors[cur]) + b*NN;
    for (int x = t; x < NN; x += 512) sc[x] = C[x];
    for (int x = t; x < 1024; x += 512) hist[x] = 0u;
    __syncthreads();

    float2 ci = sc[il];
    u64 key[2]; unsigned bin[2];
    #pragma unroll
    for (int r = 0; r < 2; r++){
        int x = t + 512*r;
        float dx = ci.x - sc[x].x, dy = ci.y - sc[x].y;
        float d = dx*dx + dy*dy;
        unsigned db = __float_as_uint(d);
        key[r] = ((u64)db << 32) | (unsigned)x;
        bin[r] = min(db >> 22, 1023u);
        atomicAdd(&hist[bin[r]], 1u);
    }
    __syncthreads();

    unsigned lane = t & 31, w = t >> 5;    // w in 0..15
    unsigned local = hist[2*t] + hist[2*t+1];
    unsigned v = local;
    #pragma unroll
    for (int off = 1; off < 32; off <<= 1){
        unsigned nv = __shfl_up_sync(0xffffffffu, v, off);
        if (lane >= off) v += nv;
    }
    if (lane == 31) sScan[w] = v;
    __syncthreads();
    unsigned wb = 0;
    #pragma unroll
    for (int i = 0; i < 16; i++) if (i < (int)w) wb += sScan[i];
    unsigned run = wb + v - local;         // exclusive prefix of this thread's first bin
    #pragma unroll
    for (int q = 0; q < 2; q++){
        unsigned h = hist[2*t + q];
        if (run <= 127u && run + h > 127u){ sT = 2*t + q; sNeed = 128u - run; }
        run += h;
    }
    __syncthreads();
    unsigned T = sT, need = sNeed;

    unsigned winbase = 0, candbase = 0;
    unsigned ltmask = (1u << lane) - 1u;
    #pragma unroll
    for (int r = 0; r < 2; r++){
        bool win = bin[r] < T;
        bool cd  = bin[r] == T;
        unsigned mw = __ballot_sync(0xffffffffu, win);
        unsigned mc = __ballot_sync(0xffffffffu, cd);
        if (lane == 0){ sWarp[w][0] = __popc(mw); sWarp[w][1] = __popc(mc); }
        __syncthreads();
        unsigned bw = winbase, bc = candbase, tw = 0, tc = 0;
        #pragma unroll
        for (int i = 0; i < 16; i++){
            unsigned cw_ = sWarp[i][0], cc_ = sWarp[i][1];
            if (i < (int)w){ bw += cw_; bc += cc_; }
            tw += cw_; tc += cc_;
        }
        if (win){
            unsigned pos = bw + __popc(mw & ltmask);
            g_idx [gi*KK + pos] = (int)(key[r] & 0xffffffffull);
            g_dist[gi*KK + pos] = __uint_as_float((unsigned)(key[r] >> 32));
        }
        if (cd){
            unsigned pos = bc + __popc(mc & ltmask);
            cand[pos] = key[r];
        }
        winbase += tw; candbase += tc;
        __syncthreads();
    }

    unsigned cntT = candbase;
    unsigned P = 2; while (P < cntT) P <<= 1;
    for (unsigned x = cntT + t; x < P; x += 512) cand[x] = 0xffffffffffffffffull;
    __syncthreads();
    for (unsigned k = 2; k <= P; k <<= 1){
        for (unsigned j = k >> 1; j > 0; j >>= 1){
            for (unsigned x = t; x < P; x += 512){
                unsigned ixj = x ^ j;
                if (ixj > x){
                    u64 a = cand[x], bb = cand[ixj];
                    bool up = (x & k) == 0;
                    if ((a > bb) == up){ cand[x] = bb; cand[ixj] = a; }
                }
            }
            __syncthreads();
        }
    }
    if (t < need){
        u64 kv = cand[t];
        unsigned pos = winbase + t;
        g_idx [gi*KK + pos] = (int)(kv & 0xffffffffull);
        g_dist[gi*KK + pos] = __uint_as_float((unsigned)(kv >> 32));
    }
}

// ================= pre body: A/Bv projections, 128 threads/node =================
__device__ __forceinline__ void pre_body(int gi, int n, int tn, const float ff[4][DD],
                                         const float* __restrict__ e1w,
                                         const float* __restrict__ e1b){
    for (int u = tn; u < EHP; u += 128){
        float a = 0.f, bv = 0.f;
        if (u < EH){
            a = e1b[u];
            #pragma unroll
            for (int r = 0; r < DD; r++){
                float fr = ff[n][r];
                a  += fr * e1w[r*EH + u];
                bv += fr * e1w[(DD + r)*EH + u];
            }
        }
        g_A [gi*EHP + u] = a;
        g_Bv[gi*EHP + u] = bv;
    }
}

// ================= embed + pre body (nodes = blockDim/128, 128 thr each) =================
__device__ void embed_pre_body(int giBase,
                               const float* __restrict__ feat,
                               const float* __restrict__ ew, const float* __restrict__ eb,
                               const float* __restrict__ e1w, const float* __restrict__ e1b){
    __shared__ float fin[4][DD], ff[4][DD];
    int t = threadIdx.x;
    int n = t >> 7, tn = t & 127;
    int gi = giBase + n;
    if (tn < DD) fin[n][tn] = feat[gi*DD + tn];
    __syncthreads();
    if (tn < DD){
        float a = eb[tn];
        #pragma unroll
        for (int r = 0; r < DD; r++) a += fin[n][r]*ew[r*DD + tn];
        float o = lrelu(a);
        g_feats[0][gi*DD + tn] = o;
        ff[n][tn] = o;
    }
    __syncthreads();
    pre_body(gi, n, tn, ff, e1w, e1b);
}

// ================= node MLP + residual (+pre of next layer) =================
__device__ void node_pre_body(int giBase, int cur, int last, float* __restrict__ dout,
                              const float* __restrict__ n1w, const float* __restrict__ n1b,
                              const float* __restrict__ n2w, const float* __restrict__ n2b,
                              const float* __restrict__ e1w, const float* __restrict__ e1b){
    __shared__ float in[4][2*DD], h[4][2*DD], ff[4][DD];
    int t = threadIdx.x;
    int n = t >> 7, tn = t & 127;
    int gi = giBase + n;
    if (tn < 2*DD)
        in[n][tn] = (tn < DD) ? g_feats[cur][gi*DD + tn] : g_msum[gi*DD + (tn - DD)];
    __syncthreads();
    if (tn < 2*DD){
        float a = n1b[tn];
        #pragma unroll
        for (int r = 0; r < 2*DD; r++) a += in[n][r]*n1w[r*64 + tn];
        h[n][tn] = lrelu(a);
    }
    __syncthreads();
    if (tn < DD){
        float o = n2b[tn];
        #pragma unroll
        for (int r = 0; r < 2*DD; r++) o += h[n][r]*n2w[r*DD + tn];
        o += in[n][tn];
        if (last) dout[gi*DD + tn] = o;
        else { g_feats[cur^1][gi*DD + tn] = o; ff[n][tn] = o; }
    }
    if (last) return;                  // uniform across block
    __syncthreads();
    pre_body(gi, n, tn, ff, e1w, e1b);
}

// ================= fused launchers (512 threads) =================
// blocks [0,BN): knn for node blockIdx; blocks [BN, BN+BN/4): embed_pre for 4-node group
__global__ void __launch_bounds__(512)
embed_knn_kernel(int knnCur,
                 const float* __restrict__ feat,
                 const float* __restrict__ ew, const float* __restrict__ eb,
                 const float* __restrict__ e1w, const float* __restrict__ e1b){
    if (blockIdx.x < BN) knn_body(blockIdx.x, knnCur);
    else embed_pre_body((blockIdx.x - BN)*4, feat, ew, eb, e1w, e1b);
}

// blocks [0,BN): knn; blocks [BN, BN+BN/4): node_pre for 4-node group
__global__ void __launch_bounds__(512)
node_knn_kernel(int npCur, int knnCur,
                const float* __restrict__ n1w, const float* __restrict__ n1b,
                const float* __restrict__ n2w, const float* __restrict__ n2b,
                const float* __restrict__ e1w, const float* __restrict__ e1b){
    if (blockIdx.x < BN) knn_body(blockIdx.x, knnCur);
    else node_pre_body((blockIdx.x - BN)*4, npCur, 0, (float*)0, n1w, n1b, n2w, n2b, e1w, e1b);
}

// final node MLP only (writes d_out): 2 nodes/block, 256 threads
__global__ void __launch_bounds__(256)
node_last_kernel(int cur, float* __restrict__ dout,
                 const float* __restrict__ n1w, const float* __restrict__ n1b,
                 const float* __restrict__ n2w, const float* __restrict__ n2b){
    node_pre_body(blockIdx.x*2, cur, 1, dout, n1w, n1b, n2w, n2b, (const float*)0, (const float*)0);
}

// ---------------- edge kernel: R8 known-good (4 nodes/block, 4 edges/thread) ----------------
__global__ void __launch_bounds__(128)
edge_kernel(int cur,
            const float* __restrict__ e1w, const float* __restrict__ e2w,
            const float* __restrict__ e2b, const float* __restrict__ gw,
            const float* __restrict__ gb,  const float* __restrict__ c1w,
            const float* __restrict__ c1b, const float* __restrict__ c2w,
            const float* __restrict__ c2b, const float* __restrict__ scl){
    __shared__ __align__(16) float sW2[EHP*DD];     // e2 weights [u][dd]
    __shared__ __align__(16) float sC1t[KK*36];     // c1 transposed [v][dd], stride 36
    __shared__ __align__(16) float sA[4][EHP];
    __shared__ __align__(16) float sW1c[EHP];
    __shared__ __align__(16) float sC2[KK];
    __shared__ __align__(16) float sC1b[KK];
    __shared__ __align__(16) float sGw[DD];
    __shared__ __align__(16) float sE2b[DD];

    int t = threadIdx.x;
    int w = t >> 5;                    // warp = node within block
    int lane = t & 31;
    int gi = blockIdx.x*4 + w;
    int b = gi >> 10;

    for (int x = t; x < EHP*DD; x += 128) sW2[x] = (x < EH*DD) ? e2w[x] : 0.f;
    for (int x = t; x < DD*KK; x += 128){ int dd = x >> 7, v = x & 127; sC1t[v*36 + dd] = c1w[x]; }
    for (int x = t; x < 4*EHP; x += 128){
        int n = x / EHP, u = x - n*EHP;
        sA[n][u] = g_A[(blockIdx.x*4 + n)*EHP + u];
    }
    for (int x = t; x < EHP; x += 128) sW1c[x] = (x < EH) ? e1w[64*EH + x] : 0.f;
    if (t < KK){ sC2[t] = c2w[t]; sC1b[t] = c1b[t]; }
    if (t < DD){ sGw[t] = gw[t]; sE2b[t] = e2b[t]; }
    __syncthreads();

    int   j[4]; float d[4];
    #pragma unroll
    for (int q = 0; q < 4; q++){
        j[q] = g_idx [gi*KK + lane + 32*q];
        d[q] = g_dist[gi*KK + lane + 32*q];
    }
    const float4* bvP[4];
    #pragma unroll
    for (int q = 0; q < 4; q++)
        bvP[q] = (const float4*)(g_Bv + (size_t)(b*NN + j[q])*EHP);

    const float4* a4p = (const float4*)(sA[w]);
    const float4* w4p = (const float4*)(sW1c);
    const u64* gw2 = (const u64*)sGw;

    u64 m[4][16];
    {
        const u64* b2 = (const u64*)sE2b;
        #pragma unroll
        for (int q = 0; q < 4; q++)
            #pragma unroll
            for (int i = 0; i < 16; i++) m[q][i] = b2[i];
    }

    // software-pipelined main loop
    float4 bvCur[4];
    #pragma unroll
    for (int q = 0; q < 4; q++) bvCur[q] = bvP[q][0];

    #pragma unroll 1
    for (int g = 0; g < EHP/4; g++){
        float4 bvNext[4];
        if (g + 1 < EHP/4){
            #pragma unroll
            for (int q = 0; q < 4; q++) bvNext[q] = bvP[q][g+1];
        }
        float4 aa = a4p[g], wc = w4p[g];
        float av[4] = {aa.x, aa.y, aa.z, aa.w};
        float wv[4] = {wc.x, wc.y, wc.z, wc.w};
        float bv[4][4];
        #pragma unroll
        for (int q = 0; q < 4; q++){
            bv[q][0] = bvCur[q].x; bv[q][1] = bvCur[q].y;
            bv[q][2] = bvCur[q].z; bv[q][3] = bvCur[q].w;
        }
        #pragma unroll
        for (int s = 0; s < 4; s++){
            int u = 4*g + s;
            u64 h2[4];
            #pragma unroll
            for (int q = 0; q < 4; q++){
                float h = lrelu(fmaf(d[q], wv[s], av[s]) + bv[q][s]);
                h2[q] = pk2(h, h);
            }
            const ulonglong2* w2 = (const ulonglong2*)(sW2 + u*DD);
            #pragma unroll
            for (int k = 0; k < 8; k++){
                ulonglong2 ww = w2[k];
                #pragma unroll
                for (int q = 0; q < 4; q++){
                    m[q][2*k]   = fma2_(h2[q], ww.x, m[q][2*k]);
                    m[q][2*k+1] = fma2_(h2[q], ww.y, m[q][2*k+1]);
                }
            }
        }
        #pragma unroll
        for (int q = 0; q < 4; q++) bvCur[q] = bvNext[q];
    }

    // lrelu on messages
    #pragma unroll
    for (int q = 0; q < 4; q++)
        #pragma unroll
        for (int i = 0; i < 16; i++){
            float2 f = upk2(m[q][i]);
            m[q][i] = pk2(lrelu(f.x), lrelu(f.y));
        }

    // soft-edge gates
    float gb0 = gb[0];
    {
        u64 acc[4] = {0ull,0ull,0ull,0ull};
        #pragma unroll
        for (int i = 0; i < 16; i++){
            u64 gwv = gw2[i];
            #pragma unroll
            for (int q = 0; q < 4; q++) acc[q] = fma2_(m[q][i], gwv, acc[q]);
        }
        #pragma unroll
        for (int q = 0; q < 4; q++){
            float2 a = upk2(acc[q]);
            float sg = 1.f/(1.f + expf(-(gb0 + a.x + a.y)));
            u64 sg2 = pk2(sg, sg);
            #pragma unroll
            for (int i = 0; i < 16; i++) m[q][i] = mul2_(m[q][i], sg2);
        }
    }

    // coors MLP -> per-edge scalar weight; 2 c1 rows per iteration for ILP
    float c2b0 = c2b[0];
    float cw[4] = {c2b0, c2b0, c2b0, c2b0};
    #pragma unroll 1
    for (int vp = 0; vp < KK/2; vp++){
        const ulonglong2* ccA = (const ulonglong2*)(sC1t + (2*vp)*36);
        const ulonglong2* ccB = (const ulonglong2*)(sC1t + (2*vp+1)*36);
        u64 sa[4] = {0ull,0ull,0ull,0ull};
        u64 sb[4] = {0ull,0ull,0ull,0ull};
        #pragma unroll
        for (int k = 0; k < 8; k++){
            ulonglong2 wa = ccA[k], wb = ccB[k];
            #pragma unroll
            for (int q = 0; q < 4; q++){
                sa[q] = fma2_(m[q][2*k],   wa.x, sa[q]);
                sa[q] = fma2_(m[q][2*k+1], wa.y, sa[q]);
                sb[q] = fma2_(m[q][2*k],   wb.x, sb[q]);
                sb[q] = fma2_(m[q][2*k+1], wb.y, sb[q]);
            }
        }
        float2 cb2 = ((const float2*)sC1b)[vp];
        float2 c22 = ((const float2*)sC2)[vp];
        #pragma unroll
        for (int q = 0; q < 4; q++){
            float2 fa = upk2(sa[q]), fb = upk2(sb[q]);
            cw[q] += lrelu(cb2.x + fa.x + fa.y)*c22.x;
            cw[q] += lrelu(cb2.y + fb.x + fb.y)*c22.y;
        }
    }

    // coordinate contributions
    const float2* Cg = (const float2*)(g_coors[cur]);
    float2 ci = Cg[gi];
    float sscl = scl[0];
    float cx = 0.f, cy = 0.f;
    #pragma unroll
    for (int q = 0; q < 4; q++){
        float2 cj = Cg[b*NN + j[q]];
        float rx = ci.x - cj.x, ry = ci.y - cj.y;
        float nm = fmaxf(sqrtf(rx*rx + ry*ry), 1e-8f);
        float ss = sscl/nm;
        cx += cw[q]*(rx*ss);
        cy += cw[q]*(ry*ss);
    }

    // warp-level reduction (node fully inside this warp)
    u64 mt[16];
    #pragma unroll
    for (int i = 0; i < 16; i++)
        mt[i] = add2_(add2_(m[0][i], m[1][i]), add2_(m[2][i], m[3][i]));
    u64 cp = pk2(cx, cy);
    #pragma unroll
    for (int off = 16; off > 0; off >>= 1){
        #pragma unroll
        for (int i = 0; i < 16; i++)
            mt[i] = add2_(mt[i], __shfl_xor_sync(0xffffffffu, mt[i], off));
        cp = add2_(cp, __shfl_xor_sync(0xffffffffu, cp, off));
    }
    if (lane < 16)
        ((u64*)(g_msum + (size_t)gi*DD))[lane] = mt[lane];
    if (lane == 0){
        float2 cf = upk2(cp);
        ((float2*)g_coors[cur^1])[gi] = make_float2(ci.x + cf.x, ci.y + cf.y);
    }
}

extern "C" void kernel_launch(void* const* d_in, const int* in_sizes, int n_in,
                              void* d_out, int out_size){
    const float* feat = (const float*)d_in[0];
    const float* coor = (const float*)d_in[1];
    // d_in[2] = batch (equal-size graphs; unused)
    const float* ew  = (const float*)d_in[3];
    const float* eb  = (const float*)d_in[4];
    const float* e1w = (const float*)d_in[5];
    const float* e1b = (const float*)d_in[6];
    const float* e2w = (const float*)d_in[7];
    const float* e2b = (const float*)d_in[8];
    const float* gw  = (const float*)d_in[9];
    const float* gb  = (const float*)d_in[10];
    const float* c1w = (const float*)d_in[11];
    const float* c1b = (const float*)d_in[12];
    const float* c2w = (const float*)d_in[13];
    const float* c2b = (const float*)d_in[14];
    const float* n1w = (const float*)d_in[15];
    const float* n1b = (const float*)d_in[16];
    const float* n2w = (const float*)d_in[17];
    const float* n2b = (const float*)d_in[18];
    const float* scl = (const float*)d_in[19];

    cudaMemcpyToSymbolAsync(g_coors, coor, BN*2*sizeof(float), 0,
                            cudaMemcpyDeviceToDevice, 0);

    // layer 0: knn(0) fused with embed+pre(0)
    embed_knn_kernel<<<BN + BN/4, 512>>>(0, feat, ew, eb, e1w, e1b);
    edge_kernel<<<BN/4, 128>>>(0,
                             e1w, e2w, e2b, gw, gb, c1w, c1b, c2w, c2b, scl);

    // boundaries: node_pre(l) fused with knn(l+1)
    for (int l = 1; l < 3; l++){
        int npCur = (l-1) & 1;         // buffer the previous layer computed into
        int knnCur = l & 1;            // coords written by previous edge
        node_knn_kernel<<<BN + BN/4, 512>>>(npCur, knnCur,
                                  n1w + (l-1)*64*64, n1b + (l-1)*64,
                                  n2w + (l-1)*64*DD, n2b + (l-1)*DD,
                                  e1w + l*65*EH, e1b + l*EH);
        edge_kernel<<<BN/4, 128>>>(knnCur,
                                 e1w + l*65*EH, e2w + l*EH*DD, e2b + l*DD,
                                 gw + l*DD, gb + l,
                                 c1w + l*DD*KK, c1b + l*KK,
                                 c2w + l*KK, c2b + l, scl + l);
    }

    // final node MLP -> d_out
    node_last_kernel<<<BN/2, 256>>>(0, (float*)d_out,
                              n1w + 2*64*64, n1b + 2*64,
                              n2w + 2*64*DD, n2b + 2*DD);
}

// round 15
// speedup vs baseline: 1.1152x; 1.1152x over previous
#include <cuda_runtime.h>
#include <math.h>

#define BN 4096      // total nodes (B*N)
#define NN 1024      // nodes per graph
#define KK 128       // neighbours
#define DD 32        // feature dim
#define EH 130       // edge hidden
#define EHP 132      // padded edge hidden (mult of 4)

typedef unsigned long long u64;

__device__ float g_feats[2][BN*DD];
__device__ float g_coors[2][BN*2];
__device__ int   g_idx[BN*KK];
__device__ float g_dist[BN*KK];
__device__ float g_A[BN*EHP];
__device__ float g_Bv[BN*EHP];
__device__ float g_msum[BN*DD];

__device__ __forceinline__ float lrelu(float x){ return fmaxf(x, 0.1f*x); }

__device__ __forceinline__ u64 pk2(float lo, float hi){
    u64 r; asm("mov.b64 %0, {%1,%2};" : "=l"(r) : "f"(lo), "f"(hi)); return r;
}
__device__ __forceinline__ float2 upk2(u64 v){
    float2 f; asm("mov.b64 {%0,%1}, %2;" : "=f"(f.x), "=f"(f.y) : "l"(v)); return f;
}
__device__ __forceinline__ u64 fma2_(u64 a, u64 b, u64 c){
    u64 d; asm("fma.rn.f32x2 %0, %1, %2, %3;" : "=l"(d) : "l"(a), "l"(b), "l"(c)); return d;
}
__device__ __forceinline__ u64 add2_(u64 a, u64 b){
    u64 d; asm("add.rn.f32x2 %0, %1, %2;" : "=l"(d) : "l"(a), "l"(b)); return d;
}
__device__ __forceinline__ u64 mul2_(u64 a, u64 b){
    u64 d; asm("mul.rn.f32x2 %0, %1, %2;" : "=l"(d) : "l"(a), "l"(b)); return d;
}

// ================= knn body: exact top-128 via 10-bit radix select (256 thr) =================
__device__ void knn_body(int gi, int cur){
    __shared__ float2 sc[NN];
    __shared__ unsigned int hist[1024];
    __shared__ u64 cand[NN];
    __shared__ unsigned int sWarp[8][2];
    __shared__ unsigned int sScan[8];
    __shared__ unsigned int sT, sNeed;

    int t = threadIdx.x;
    int b = gi >> 10, il = gi & 1023;
    const float2* C = (const float2*)(g_coors[cur]) + b*NN;
    for (int x = t; x < NN; x += 256) sc[x] = C[x];
    for (int x = t; x < 1024; x += 256) hist[x] = 0u;
    __syncthreads();

    float2 ci = sc[il];
    u64 key[4]; unsigned bin[4];
    #pragma unroll
    for (int r = 0; r < 4; r++){
        int x = t + 256*r;
        float dx = ci.x - sc[x].x, dy = ci.y - sc[x].y;
        float d = dx*dx + dy*dy;
        unsigned db = __float_as_uint(d);
        key[r] = ((u64)db << 32) | (unsigned)x;
        bin[r] = min(db >> 22, 1023u);
        atomicAdd(&hist[bin[r]], 1u);
    }
    __syncthreads();

    unsigned lane = t & 31, w = t >> 5;
    unsigned local = hist[4*t] + hist[4*t+1] + hist[4*t+2] + hist[4*t+3];
    unsigned v = local;
    #pragma unroll
    for (int off = 1; off < 32; off <<= 1){
        unsigned nv = __shfl_up_sync(0xffffffffu, v, off);
        if (lane >= off) v += nv;
    }
    if (lane == 31) sScan[w] = v;
    __syncthreads();
    unsigned wb = 0;
    #pragma unroll
    for (int i = 0; i < 8; i++) if (i < (int)w) wb += sScan[i];
    unsigned run = wb + v - local;
    #pragma unroll
    for (int q = 0; q < 4; q++){
        unsigned h = hist[4*t + q];
        if (run <= 127u && run + h > 127u){ sT = 4*t + q; sNeed = 128u - run; }
        run += h;
    }
    __syncthreads();
    unsigned T = sT, need = sNeed;

    unsigned winbase = 0, candbase = 0;
    unsigned ltmask = (1u << lane) - 1u;
    #pragma unroll
    for (int r = 0; r < 4; r++){
        bool win = bin[r] < T;
        bool cd  = bin[r] == T;
        unsigned mw = __ballot_sync(0xffffffffu, win);
        unsigned mc = __ballot_sync(0xffffffffu, cd);
        if (lane == 0){ sWarp[w][0] = __popc(mw); sWarp[w][1] = __popc(mc); }
        __syncthreads();
        unsigned bw = winbase, bc = candbase, tw = 0, tc = 0;
        #pragma unroll
        for (int i = 0; i < 8; i++){
            unsigned cw_ = sWarp[i][0], cc_ = sWarp[i][1];
            if (i < (int)w){ bw += cw_; bc += cc_; }
            tw += cw_; tc += cc_;
        }
        if (win){
            unsigned pos = bw + __popc(mw & ltmask);
            g_idx [gi*KK + pos] = (int)(key[r] & 0xffffffffull);
            g_dist[gi*KK + pos] = __uint_as_float((unsigned)(key[r] >> 32));
        }
        if (cd){
            unsigned pos = bc + __popc(mc & ltmask);
            cand[pos] = key[r];
        }
        winbase += tw; candbase += tc;
        __syncthreads();
    }

    unsigned cntT = candbase;
    unsigned P = 2; while (P < cntT) P <<= 1;
    for (unsigned x = cntT + t; x < P; x += 256) cand[x] = 0xffffffffffffffffull;
    __syncthreads();
    for (unsigned k = 2; k <= P; k <<= 1){
        for (unsigned j = k >> 1; j > 0; j >>= 1){
            for (unsigned x = t; x < P; x += 256){
                unsigned ixj = x ^ j;
                if (ixj > x){
                    u64 a = cand[x], bb = cand[ixj];
                    bool up = (x & k) == 0;
                    if ((a > bb) == up){ cand[x] = bb; cand[ixj] = a; }
                }
            }
            __syncthreads();
        }
    }
    if (t < need){
        u64 kv = cand[t];
        unsigned pos = winbase + t;
        g_idx [gi*KK + pos] = (int)(kv & 0xffffffffull);
        g_dist[gi*KK + pos] = __uint_as_float((unsigned)(kv >> 32));
    }
}

// ================= pre body: A/Bv projections, 2 nodes x 128 threads =================
__device__ __forceinline__ void pre_body(int gi, int n, int tn, const float ff[2][DD],
                                         const float* __restrict__ e1w,
                                         const float* __restrict__ e1b){
    for (int u = tn; u < EHP; u += 128){
        float a = 0.f, bv = 0.f;
        if (u < EH){
            a = e1b[u];
            #pragma unroll
            for (int r = 0; r < DD; r++){
                float fr = ff[n][r];
                a  += fr * e1w[r*EH + u];
                bv += fr * e1w[(DD + r)*EH + u];
            }
        }
        g_A [gi*EHP + u] = a;
        g_Bv[gi*EHP + u] = bv;
    }
}

// ================= embed + pre body (2 nodes x 128 threads) =================
__device__ void embed_pre_body(int pair,
                               const float* __restrict__ feat,
                               const float* __restrict__ ew, const float* __restrict__ eb,
                               const float* __restrict__ e1w, const float* __restrict__ e1b){
    __shared__ float fin[2][DD], ff[2][DD];
    int t = threadIdx.x;
    int n = t >> 7, tn = t & 127;
    int gi = pair*2 + n;
    if (tn < DD) fin[n][tn] = feat[gi*DD + tn];
    __syncthreads();
    if (tn < DD){
        float a = eb[tn];
        #pragma unroll
        for (int r = 0; r < DD; r++) a += fin[n][r]*ew[r*DD + tn];
        float o = lrelu(a);
        g_feats[0][gi*DD + tn] = o;
        ff[n][tn] = o;
    }
    __syncthreads();
    pre_body(gi, n, tn, ff, e1w, e1b);
}

// ================= node MLP + residual (+pre of next layer), 2 nodes x 128 threads =================
__device__ void node_pre_body(int pair, int cur, int last, float* __restrict__ dout,
                              const float* __restrict__ n1w, const float* __restrict__ n1b,
                              const float* __restrict__ n2w, const float* __restrict__ n2b,
                              const float* __restrict__ e1w, const float* __restrict__ e1b){
    __shared__ float in[2][2*DD], h[2][2*DD], ff[2][DD];
    int t = threadIdx.x;
    int n = t >> 7, tn = t & 127;
    int gi = pair*2 + n;
    if (tn < 2*DD)
        in[n][tn] = (tn < DD) ? g_feats[cur][gi*DD + tn] : g_msum[gi*DD + (tn - DD)];
    __syncthreads();
    if (tn < 2*DD){
        float a = n1b[tn];
        #pragma unroll
        for (int r = 0; r < 2*DD; r++) a += in[n][r]*n1w[r*64 + tn];
        h[n][tn] = lrelu(a);
    }
    __syncthreads();
    if (tn < DD){
        float o = n2b[tn];
        #pragma unroll
        for (int r = 0; r < 2*DD; r++) o += h[n][r]*n2w[r*DD + tn];
        o += in[n][tn];
        if (last) dout[gi*DD + tn] = o;
        else { g_feats[cur^1][gi*DD + tn] = o; ff[n][tn] = o; }
    }
    if (last) return;                  // uniform across block
    __syncthreads();
    pre_body(gi, n, tn, ff, e1w, e1b);
}

// ================= fused launchers =================
// blocks [0,BN): knn for node blockIdx (reads coors[knnCur])
// blocks [BN, BN+BN/2): embed_pre for pair blockIdx-BN
__global__ void __launch_bounds__(256)
embed_knn_kernel(int knnCur,
                 const float* __restrict__ feat,
                 const float* __restrict__ ew, const float* __restrict__ eb,
                 const float* __restrict__ e1w, const float* __restrict__ e1b){
    if (blockIdx.x < BN) knn_body(blockIdx.x, knnCur);
    else embed_pre_body(blockIdx.x - BN, feat, ew, eb, e1w, e1b);
}

// blocks [0,BN): knn (reads coors[knnCur] = coors written by previous edge)
// blocks [BN, BN+BN/2): node_pre for the just-finished layer (cur = npCur)
__global__ void __launch_bounds__(256)
node_knn_kernel(int npCur, int knnCur,
                const float* __restrict__ n1w, const float* __restrict__ n1b,
                const float* __restrict__ n2w, const float* __restrict__ n2b,
                const float* __restrict__ e1w, const float* __restrict__ e1b){
    if (blockIdx.x < BN) knn_body(blockIdx.x, knnCur);
    else node_pre_body(blockIdx.x - BN, npCur, 0, (float*)0, n1w, n1b, n2w, n2b, e1w, e1b);
}

// final node MLP only (writes d_out)
__global__ void __launch_bounds__(256)
node_last_kernel(int cur, float* __restrict__ dout,
                 const float* __restrict__ n1w, const float* __restrict__ n1b,
                 const float* __restrict__ n2w, const float* __restrict__ n2b){
    node_pre_body(blockIdx.x, cur, 1, dout, n1w, n1b, n2w, n2b, (const float*)0, (const float*)0);
}

// ---------------- edge kernel: R8 known-good (4 nodes/block, 4 edges/thread) ----------------
__global__ void __launch_bounds__(128)
edge_kernel(int cur,
            const float* __restrict__ e1w, const float* __restrict__ e2w,
            const float* __restrict__ e2b, const float* __restrict__ gw,
            const float* __restrict__ gb,  const float* __restrict__ c1w,
            const float* __restrict__ c1b, const float* __restrict__ c2w,
            const float* __restrict__ c2b, const float* __restrict__ scl){
    __shared__ __align__(16) float sW2[EHP*DD];     // e2 weights [u][dd]
    __shared__ __align__(16) float sC1t[KK*36];     // c1 transposed [v][dd], stride 36
    __shared__ __align__(16) float sA[4][EHP];
    __shared__ __align__(16) float sW1c[EHP];
    __shared__ __align__(16) float sC2[KK];
    __shared__ __align__(16) float sC1b[KK];
    __shared__ __align__(16) float sGw[DD];
    __shared__ __align__(16) float sE2b[DD];

    int t = threadIdx.x;
    int w = t >> 5;                    // warp = node within block
    int lane = t & 31;
    int gi = blockIdx.x*4 + w;
    int b = gi >> 10;

    for (int x = t; x < EHP*DD; x += 128) sW2[x] = (x < EH*DD) ? e2w[x] : 0.f;
    for (int x = t; x < DD*KK; x += 128){ int dd = x >> 7, v = x & 127; sC1t[v*36 + dd] = c1w[x]; }
    for (int x = t; x < 4*EHP; x += 128){
        int n = x / EHP, u = x - n*EHP;
        sA[n][u] = g_A[(blockIdx.x*4 + n)*EHP + u];
    }
    for (int x = t; x < EHP; x += 128) sW1c[x] = (x < EH) ? e1w[64*EH + x] : 0.f;
    if (t < KK){ sC2[t] = c2w[t]; sC1b[t] = c1b[t]; }
    if (t < DD){ sGw[t] = gw[t]; sE2b[t] = e2b[t]; }
    __syncthreads();

    int   j[4]; float d[4];
    #pragma unroll
    for (int q = 0; q < 4; q++){
        j[q] = g_idx [gi*KK + lane + 32*q];
        d[q] = g_dist[gi*KK + lane + 32*q];
    }
    const float4* bvP[4];
    #pragma unroll
    for (int q = 0; q < 4; q++)
        bvP[q] = (const float4*)(g_Bv + (size_t)(b*NN + j[q])*EHP);

    const float4* a4p = (const float4*)(sA[w]);
    const float4* w4p = (const float4*)(sW1c);
    const u64* gw2 = (const u64*)sGw;

    u64 m[4][16];
    {
        const u64* b2 = (const u64*)sE2b;
        #pragma unroll
        for (int q = 0; q < 4; q++)
            #pragma unroll
            for (int i = 0; i < 16; i++) m[q][i] = b2[i];
    }

    // software-pipelined main loop
    float4 bvCur[4];
    #pragma unroll
    for (int q = 0; q < 4; q++) bvCur[q] = bvP[q][0];

    #pragma unroll 1
    for (int g = 0; g < EHP/4; g++){
        float4 bvNext[4];
        if (g + 1 < EHP/4){
            #pragma unroll
            for (int q = 0; q < 4; q++) bvNext[q] = bvP[q][g+1];
        }
        float4 aa = a4p[g], wc = w4p[g];
        float av[4] = {aa.x, aa.y, aa.z, aa.w};
        float wv[4] = {wc.x, wc.y, wc.z, wc.w};
        float bv[4][4];
        #pragma unroll
        for (int q = 0; q < 4; q++){
            bv[q][0] = bvCur[q].x; bv[q][1] = bvCur[q].y;
            bv[q][2] = bvCur[q].z; bv[q][3] = bvCur[q].w;
        }
        #pragma unroll
        for (int s = 0; s < 4; s++){
            int u = 4*g + s;
            u64 h2[4];
            #pragma unroll
            for (int q = 0; q < 4; q++){
                float h = lrelu(fmaf(d[q], wv[s], av[s]) + bv[q][s]);
                h2[q] = pk2(h, h);
            }
            const ulonglong2* w2 = (const ulonglong2*)(sW2 + u*DD);
            #pragma unroll
            for (int k = 0; k < 8; k++){
                ulonglong2 ww = w2[k];
                #pragma unroll
                for (int q = 0; q < 4; q++){
                    m[q][2*k]   = fma2_(h2[q], ww.x, m[q][2*k]);
                    m[q][2*k+1] = fma2_(h2[q], ww.y, m[q][2*k+1]);
                }
            }
        }
        #pragma unroll
        for (int q = 0; q < 4; q++) bvCur[q] = bvNext[q];
    }

    // lrelu on messages
    #pragma unroll
    for (int q = 0; q < 4; q++)
        #pragma unroll
        for (int i = 0; i < 16; i++){
            float2 f = upk2(m[q][i]);
            m[q][i] = pk2(lrelu(f.x), lrelu(f.y));
        }

    // soft-edge gates
    float gb0 = gb[0];
    {
        u64 acc[4] = {0ull,0ull,0ull,0ull};
        #pragma unroll
        for (int i = 0; i < 16; i++){
            u64 gwv = gw2[i];
            #pragma unroll
            for (int q = 0; q < 4; q++) acc[q] = fma2_(m[q][i], gwv, acc[q]);
        }
        #pragma unroll
        for (int q = 0; q < 4; q++){
            float2 a = upk2(acc[q]);
            float sg = 1.f/(1.f + expf(-(gb0 + a.x + a.y)));
            u64 sg2 = pk2(sg, sg);
            #pragma unroll
            for (int i = 0; i < 16; i++) m[q][i] = mul2_(m[q][i], sg2);
        }
    }

    // coors MLP -> per-edge scalar weight; 2 c1 rows per iteration for ILP
    float c2b0 = c2b[0];
    float cw[4] = {c2b0, c2b0, c2b0, c2b0};
    #pragma unroll 1
    for (int vp = 0; vp < KK/2; vp++){
        const ulonglong2* ccA = (const ulonglong2*)(sC1t + (2*vp)*36);
        const ulonglong2* ccB = (const ulonglong2*)(sC1t + (2*vp+1)*36);
        u64 sa[4] = {0ull,0ull,0ull,0ull};
        u64 sb[4] = {0ull,0ull,0ull,0ull};
        #pragma unroll
        for (int k = 0; k < 8; k++){
            ulonglong2 wa = ccA[k], wb = ccB[k];
            #pragma unroll
            for (int q = 0; q < 4; q++){
                sa[q] = fma2_(m[q][2*k],   wa.x, sa[q]);
                sa[q] = fma2_(m[q][2*k+1], wa.y, sa[q]);
                sb[q] = fma2_(m[q][2*k],   wb.x, sb[q]);
                sb[q] = fma2_(m[q][2*k+1], wb.y, sb[q]);
            }
        }
        float2 cb2 = ((const float2*)sC1b)[vp];
        float2 c22 = ((const float2*)sC2)[vp];
        #pragma unroll
        for (int q = 0; q < 4; q++){
            float2 fa = upk2(sa[q]), fb = upk2(sb[q]);
            cw[q] += lrelu(cb2.x + fa.x + fa.y)*c22.x;
            cw[q] += lrelu(cb2.y + fb.x + fb.y)*c22.y;
        }
    }

    // coordinate contributions
    const float2* Cg = (const float2*)(g_coors[cur]);
    float2 ci = Cg[gi];
    float sscl = scl[0];
    float cx = 0.f, cy = 0.f;
    #pragma unroll
    for (int q = 0; q < 4; q++){
        float2 cj = Cg[b*NN + j[q]];
        float rx = ci.x - cj.x, ry = ci.y - cj.y;
        float nm = fmaxf(sqrtf(rx*rx + ry*ry), 1e-8f);
        float ss = sscl/nm;
        cx += cw[q]*(rx*ss);
        cy += cw[q]*(ry*ss);
    }

    // warp-level reduction (node fully inside this warp)
    u64 mt[16];
    #pragma unroll
    for (int i = 0; i < 16; i++)
        mt[i] = add2_(add2_(m[0][i], m[1][i]), add2_(m[2][i], m[3][i]));
    u64 cp = pk2(cx, cy);
    #pragma unroll
    for (int off = 16; off > 0; off >>= 1){
        #pragma unroll
        for (int i = 0; i < 16; i++)
            mt[i] = add2_(mt[i], __shfl_xor_sync(0xffffffffu, mt[i], off));
        cp = add2_(cp, __shfl_xor_sync(0xffffffffu, cp, off));
    }
    if (lane < 16)
        ((u64*)(g_msum + (size_t)gi*DD))[lane] = mt[lane];
    if (lane == 0){
        float2 cf = upk2(cp);
        ((float2*)g_coors[cur^1])[gi] = make_float2(ci.x + cf.x, ci.y + cf.y);
    }
}

extern "C" void kernel_launch(void* const* d_in, const int* in_sizes, int n_in,
                              void* d_out, int out_size){
    const float* feat = (const float*)d_in[0];
    const float* coor = (const float*)d_in[1];
    // d_in[2] = batch (equal-size graphs; unused)
    const float* ew  = (const float*)d_in[3];
    const float* eb  = (const float*)d_in[4];
    const float* e1w = (const float*)d_in[5];
    const float* e1b = (const float*)d_in[6];
    const float* e2w = (const float*)d_in[7];
    const float* e2b = (const float*)d_in[8];
    const float* gw  = (const float*)d_in[9];
    const float* gb  = (const float*)d_in[10];
    const float* c1w = (const float*)d_in[11];
    const float* c1b = (const float*)d_in[12];
    const float* c2w = (const float*)d_in[13];
    const float* c2b = (const float*)d_in[14];
    const float* n1w = (const float*)d_in[15];
    const float* n1b = (const float*)d_in[16];
    const float* n2w = (const float*)d_in[17];
    const float* n2b = (const float*)d_in[18];
    const float* scl = (const float*)d_in[19];

    cudaMemcpyToSymbolAsync(g_coors, coor, BN*2*sizeof(float), 0,
                            cudaMemcpyDeviceToDevice, 0);

    // layer 0: knn(0) fused with embed+pre(0)
    embed_knn_kernel<<<BN + BN/2, 256>>>(0, feat, ew, eb, e1w, e1b);
    edge_kernel<<<BN/4, 128>>>(0,
                             e1w, e2w, e2b, gw, gb, c1w, c1b, c2w, c2b, scl);

    // boundaries: node_pre(l) fused with knn(l+1)
    for (int l = 1; l < 3; l++){
        int npCur = (l-1) & 1;         // buffer the previous layer computed into
        int knnCur = l & 1;            // coords written by previous edge
        node_knn_kernel<<<BN + BN/2, 256>>>(npCur, knnCur,
                                  n1w + (l-1)*64*64, n1b + (l-1)*64,
                                  n2w + (l-1)*64*DD, n2b + (l-1)*DD,
                                  e1w + l*65*EH, e1b + l*EH);
        edge_kernel<<<BN/4, 128>>>(knnCur,
                                 e1w + l*65*EH, e2w + l*EH*DD, e2b + l*DD,
                                 gw + l*DD, gb + l,
                                 c1w + l*DD*KK, c1b + l*KK,
                                 c2w + l*KK, c2b + l, scl + l);
    }

    // final node MLP -> d_out
    node_last_kernel<<<BN/2, 256>>>(0, (float*)d_out,
                              n1w + 2*64*64, n1b + 2*64,
                              n2w + 2*64*DD, n2b + 2*DD);
}

// round 16
// speedup vs baseline: 1.2084x; 1.0835x over previous
#include <cuda_runtime.h>
#include <math.h>

#define BN 4096      // total nodes (B*N)
#define NN 1024      // nodes per graph
#define KK 128       // neighbours
#define DD 32        // feature dim
#define EH 130       // edge hidden
#define EHP 132      // padded edge hidden (mult of 4)

typedef unsigned long long u64;

__device__ float g_feats[2][BN*DD];
__device__ float g_coors[2][BN*2];
__device__ int   g_idx[BN*KK];
__device__ float g_dist[BN*KK];
__device__ float g_A[BN*EHP];
__device__ float g_Bv[BN*EHP];
__device__ float g_msum[BN*DD];

__device__ __forceinline__ float lrelu(float x){ return fmaxf(x, 0.1f*x); }

__device__ __forceinline__ u64 pk2(float lo, float hi){
    u64 r; asm("mov.b64 %0, {%1,%2};" : "=l"(r) : "f"(lo), "f"(hi)); return r;
}
__device__ __forceinline__ float2 upk2(u64 v){
    float2 f; asm("mov.b64 {%0,%1}, %2;" : "=f"(f.x), "=f"(f.y) : "l"(v)); return f;
}
__device__ __forceinline__ u64 fma2_(u64 a, u64 b, u64 c){
    u64 d; asm("fma.rn.f32x2 %0, %1, %2, %3;" : "=l"(d) : "l"(a), "l"(b), "l"(c)); return d;
}
__device__ __forceinline__ u64 add2_(u64 a, u64 b){
    u64 d; asm("add.rn.f32x2 %0, %1, %2;" : "=l"(d) : "l"(a), "l"(b)); return d;
}
__device__ __forceinline__ u64 mul2_(u64 a, u64 b){
    u64 d; asm("mul.rn.f32x2 %0, %1, %2;" : "=l"(d) : "l"(a), "l"(b)); return d;
}

// ================= knn body: exact top-128 via 10-bit radix select (256 thr) =================
__device__ void knn_body(int gi, int cur){
    __shared__ float2 sc[NN];
    __shared__ unsigned int hist[1024];
    __shared__ u64 cand[NN];
    __shared__ unsigned int sWarp[8][2];
    __shared__ unsigned int sScan[8];
    __shared__ unsigned int sT, sNeed;

    int t = threadIdx.x;
    int b = gi >> 10, il = gi & 1023;
    const float2* C = (const float2*)(g_coors[cur]) + b*NN;
    for (int x = t; x < NN; x += 256) sc[x] = C[x];
    for (int x = t; x < 1024; x += 256) hist[x] = 0u;
    __syncthreads();

    float2 ci = sc[il];
    u64 key[4]; unsigned bin[4];
    #pragma unroll
    for (int r = 0; r < 4; r++){
        int x = t + 256*r;
        float dx = ci.x - sc[x].x, dy = ci.y - sc[x].y;
        float d = dx*dx + dy*dy;
        unsigned db = __float_as_uint(d);
        key[r] = ((u64)db << 32) | (unsigned)x;
        bin[r] = min(db >> 22, 1023u);
        atomicAdd(&hist[bin[r]], 1u);
    }
    __syncthreads();

    unsigned lane = t & 31, w = t >> 5;
    unsigned local = hist[4*t] + hist[4*t+1] + hist[4*t+2] + hist[4*t+3];
    unsigned v = local;
    #pragma unroll
    for (int off = 1; off < 32; off <<= 1){
        unsigned nv = __shfl_up_sync(0xffffffffu, v, off);
        if (lane >= off) v += nv;
    }
    if (lane == 31) sScan[w] = v;
    __syncthreads();
    unsigned wb = 0;
    #pragma unroll
    for (int i = 0; i < 8; i++) if (i < (int)w) wb += sScan[i];
    unsigned run = wb + v - local;
    #pragma unroll
    for (int q = 0; q < 4; q++){
        unsigned h = hist[4*t + q];
        if (run <= 127u && run + h > 127u){ sT = 4*t + q; sNeed = 128u - run; }
        run += h;
    }
    __syncthreads();
    unsigned T = sT, need = sNeed;

    unsigned winbase = 0, candbase = 0;
    unsigned ltmask = (1u << lane) - 1u;
    #pragma unroll
    for (int r = 0; r < 4; r++){
        bool win = bin[r] < T;
        bool cd  = bin[r] == T;
        unsigned mw = __ballot_sync(0xffffffffu, win);
        unsigned mc = __ballot_sync(0xffffffffu, cd);
        if (lane == 0){ sWarp[w][0] = __popc(mw); sWarp[w][1] = __popc(mc); }
        __syncthreads();
        unsigned bw = winbase, bc = candbase, tw = 0, tc = 0;
        #pragma unroll
        for (int i = 0; i < 8; i++){
            unsigned cw_ = sWarp[i][0], cc_ = sWarp[i][1];
            if (i < (int)w){ bw += cw_; bc += cc_; }
            tw += cw_; tc += cc_;
        }
        if (win){
            unsigned pos = bw + __popc(mw & ltmask);
            g_idx [gi*KK + pos] = (int)(key[r] & 0xffffffffull);
            g_dist[gi*KK + pos] = __uint_as_float((unsigned)(key[r] >> 32));
        }
        if (cd){
            unsigned pos = bc + __popc(mc & ltmask);
            cand[pos] = key[r];
        }
        winbase += tw; candbase += tc;
        __syncthreads();
    }

    unsigned cntT = candbase;
    unsigned P = 2; while (P < cntT) P <<= 1;
    for (unsigned x = cntT + t; x < P; x += 256) cand[x] = 0xffffffffffffffffull;
    __syncthreads();
    for (unsigned k = 2; k <= P; k <<= 1){
        for (unsigned j = k >> 1; j > 0; j >>= 1){
            for (unsigned x = t; x < P; x += 256){
                unsigned ixj = x ^ j;
                if (ixj > x){
                    u64 a = cand[x], bb = cand[ixj];
                    bool up = (x & k) == 0;
                    if ((a > bb) == up){ cand[x] = bb; cand[ixj] = a; }
                }
            }
            __syncthreads();
        }
    }
    if (t < need){
        u64 kv = cand[t];
        unsigned pos = winbase + t;
        g_idx [gi*KK + pos] = (int)(kv & 0xffffffffull);
        g_dist[gi*KK + pos] = __uint_as_float((unsigned)(kv >> 32));
    }
}

// ================= pre body: A/Bv projections, 2 nodes x 128 threads =================
__device__ __forceinline__ void pre_body(int gi, int n, int tn, const float ff[2][DD],
                                         const float* __restrict__ e1w,
                                         const float* __restrict__ e1b){
    for (int u = tn; u < EHP; u += 128){
        float a = 0.f, bv = 0.f;
        if (u < EH){
            a = e1b[u];
            #pragma unroll
            for (int r = 0; r < DD; r++){
                float fr = ff[n][r];
                a  += fr * e1w[r*EH + u];
                bv += fr * e1w[(DD + r)*EH + u];
            }
        }
        g_A [gi*EHP + u] = a;
        g_Bv[gi*EHP + u] = bv;
    }
}

// ================= embed + pre body (2 nodes x 128 threads) =================
__device__ void embed_pre_body(int pair,
                               const float* __restrict__ feat,
                               const float* __restrict__ ew, const float* __restrict__ eb,
                               const float* __restrict__ e1w, const float* __restrict__ e1b){
    __shared__ float fin[2][DD], ff[2][DD];
    int t = threadIdx.x;
    int n = t >> 7, tn = t & 127;
    int gi = pair*2 + n;
    if (tn < DD) fin[n][tn] = feat[gi*DD + tn];
    __syncthreads();
    if (tn < DD){
        float a = eb[tn];
        #pragma unroll
        for (int r = 0; r < DD; r++) a += fin[n][r]*ew[r*DD + tn];
        float o = lrelu(a);
        g_feats[0][gi*DD + tn] = o;
        ff[n][tn] = o;
    }
    __syncthreads();
    pre_body(gi, n, tn, ff, e1w, e1b);
}

// ================= node MLP + residual (+pre of next layer), 2 nodes x 128 threads =================
__device__ void node_pre_body(int pair, int cur, int last, float* __restrict__ dout,
                              const float* __restrict__ n1w, const float* __restrict__ n1b,
                              const float* __restrict__ n2w, const float* __restrict__ n2b,
                              const float* __restrict__ e1w, const float* __restrict__ e1b){
    __shared__ float in[2][2*DD], h[2][2*DD], ff[2][DD];
    int t = threadIdx.x;
    int n = t >> 7, tn = t & 127;
    int gi = pair*2 + n;
    if (tn < 2*DD)
        in[n][tn] = (tn < DD) ? g_feats[cur][gi*DD + tn] : g_msum[gi*DD + (tn - DD)];
    __syncthreads();
    if (tn < 2*DD){
        float a = n1b[tn];
        #pragma unroll
        for (int r = 0; r < 2*DD; r++) a += in[n][r]*n1w[r*64 + tn];
        h[n][tn] = lrelu(a);
    }
    __syncthreads();
    if (tn < DD){
        float o = n2b[tn];
        #pragma unroll
        for (int r = 0; r < 2*DD; r++) o += h[n][r]*n2w[r*DD + tn];
        o += in[n][tn];
        if (last) dout[gi*DD + tn] = o;
        else { g_feats[cur^1][gi*DD + tn] = o; ff[n][tn] = o; }
    }
    if (last) return;                  // uniform across block
    __syncthreads();
    pre_body(gi, n, tn, ff, e1w, e1b);
}

// ================= fused launchers =================
__global__ void __launch_bounds__(256)
embed_knn_kernel(int knnCur,
                 const float* __restrict__ feat,
                 const float* __restrict__ ew, const float* __restrict__ eb,
                 const float* __restrict__ e1w, const float* __restrict__ e1b){
    if (blockIdx.x < BN) knn_body(blockIdx.x, knnCur);
    else embed_pre_body(blockIdx.x - BN, feat, ew, eb, e1w, e1b);
}

__global__ void __launch_bounds__(256)
node_knn_kernel(int npCur, int knnCur,
                const float* __restrict__ n1w, const float* __restrict__ n1b,
                const float* __restrict__ n2w, const float* __restrict__ n2b,
                const float* __restrict__ e1w, const float* __restrict__ e1b){
    if (blockIdx.x < BN) knn_body(blockIdx.x, knnCur);
    else node_pre_body(blockIdx.x - BN, npCur, 0, (float*)0, n1w, n1b, n2w, n2b, e1w, e1b);
}

__global__ void __launch_bounds__(256)
node_last_kernel(int cur, float* __restrict__ dout,
                 const float* __restrict__ n1w, const float* __restrict__ n1b,
                 const float* __restrict__ n2w, const float* __restrict__ n2b){
    node_pre_body(blockIdx.x, cur, 1, dout, n1w, n1b, n2w, n2b, (const float*)0, (const float*)0);
}

// ---------------- edge kernel: R8 known-good (4 nodes/block, 4 edges/thread) ----------------
// lastLayer==1: coordinate path (c1 MLP, c2, coor update) is dead code — skipped.
__global__ void __launch_bounds__(128)
edge_kernel(int cur, int lastLayer,
            const float* __restrict__ e1w, const float* __restrict__ e2w,
            const float* __restrict__ e2b, const float* __restrict__ gw,
            const float* __restrict__ gb,  const float* __restrict__ c1w,
            const float* __restrict__ c1b, const float* __restrict__ c2w,
            const float* __restrict__ c2b, const float* __restrict__ scl){
    __shared__ __align__(16) float sW2[EHP*DD];     // e2 weights [u][dd]
    __shared__ __align__(16) float sC1t[KK*36];     // c1 transposed [v][dd], stride 36
    __shared__ __align__(16) float sA[4][EHP];
    __shared__ __align__(16) float sW1c[EHP];
    __shared__ __align__(16) float sC2[KK];
    __shared__ __align__(16) float sC1b[KK];
    __shared__ __align__(16) float sGw[DD];
    __shared__ __align__(16) float sE2b[DD];

    int t = threadIdx.x;
    int w = t >> 5;                    // warp = node within block
    int lane = t & 31;
    int gi = blockIdx.x*4 + w;
    int b = gi >> 10;

    for (int x = t; x < EHP*DD; x += 128) sW2[x] = (x < EH*DD) ? e2w[x] : 0.f;
    if (!lastLayer){
        for (int x = t; x < DD*KK; x += 128){ int dd = x >> 7, v = x & 127; sC1t[v*36 + dd] = c1w[x]; }
        if (t < KK){ sC2[t] = c2w[t]; sC1b[t] = c1b[t]; }
    }
    for (int x = t; x < 4*EHP; x += 128){
        int n = x / EHP, u = x - n*EHP;
        sA[n][u] = g_A[(blockIdx.x*4 + n)*EHP + u];
    }
    for (int x = t; x < EHP; x += 128) sW1c[x] = (x < EH) ? e1w[64*EH + x] : 0.f;
    if (t < DD){ sGw[t] = gw[t]; sE2b[t] = e2b[t]; }
    __syncthreads();

    int   j[4]; float d[4];
    #pragma unroll
    for (int q = 0; q < 4; q++){
        j[q] = g_idx [gi*KK + lane + 32*q];
        d[q] = g_dist[gi*KK + lane + 32*q];
    }
    const float4* bvP[4];
    #pragma unroll
    for (int q = 0; q < 4; q++)
        bvP[q] = (const float4*)(g_Bv + (size_t)(b*NN + j[q])*EHP);

    const float4* a4p = (const float4*)(sA[w]);
    const float4* w4p = (const float4*)(sW1c);
    const u64* gw2 = (const u64*)sGw;

    u64 m[4][16];
    {
        const u64* b2 = (const u64*)sE2b;
        #pragma unroll
        for (int q = 0; q < 4; q++)
            #pragma unroll
            for (int i = 0; i < 16; i++) m[q][i] = b2[i];
    }

    // software-pipelined main loop
    float4 bvCur[4];
    #pragma unroll
    for (int q = 0; q < 4; q++) bvCur[q] = bvP[q][0];

    #pragma unroll 1
    for (int g = 0; g < EHP/4; g++){
        float4 bvNext[4];
        if (g + 1 < EHP/4){
            #pragma unroll
            for (int q = 0; q < 4; q++) bvNext[q] = bvP[q][g+1];
        }
        float4 aa = a4p[g], wc = w4p[g];
        float av[4] = {aa.x, aa.y, aa.z, aa.w};
        float wv[4] = {wc.x, wc.y, wc.z, wc.w};
        float bv[4][4];
        #pragma unroll
        for (int q = 0; q < 4; q++){
            bv[q][0] = bvCur[q].x; bv[q][1] = bvCur[q].y;
            bv[q][2] = bvCur[q].z; bv[q][3] = bvCur[q].w;
        }
        #pragma unroll
        for (int s = 0; s < 4; s++){
            int u = 4*g + s;
            u64 h2[4];
            #pragma unroll
            for (int q = 0; q < 4; q++){
                float h = lrelu(fmaf(d[q], wv[s], av[s]) + bv[q][s]);
                h2[q] = pk2(h, h);
            }
            const ulonglong2* w2 = (const ulonglong2*)(sW2 + u*DD);
            #pragma unroll
            for (int k = 0; k < 8; k++){
                ulonglong2 ww = w2[k];
                #pragma unroll
                for (int q = 0; q < 4; q++){
                    m[q][2*k]   = fma2_(h2[q], ww.x, m[q][2*k]);
                    m[q][2*k+1] = fma2_(h2[q], ww.y, m[q][2*k+1]);
                }
            }
        }
        #pragma unroll
        for (int q = 0; q < 4; q++) bvCur[q] = bvNext[q];
    }

    // lrelu on messages
    #pragma unroll
    for (int q = 0; q < 4; q++)
        #pragma unroll
        for (int i = 0; i < 16; i++){
            float2 f = upk2(m[q][i]);
            m[q][i] = pk2(lrelu(f.x), lrelu(f.y));
        }

    // soft-edge gates
    float gb0 = gb[0];
    {
        u64 acc[4] = {0ull,0ull,0ull,0ull};
        #pragma unroll
        for (int i = 0; i < 16; i++){
            u64 gwv = gw2[i];
            #pragma unroll
            for (int q = 0; q < 4; q++) acc[q] = fma2_(m[q][i], gwv, acc[q]);
        }
        #pragma unroll
        for (int q = 0; q < 4; q++){
            float2 a = upk2(acc[q]);
            float sg = 1.f/(1.f + expf(-(gb0 + a.x + a.y)));
            u64 sg2 = pk2(sg, sg);
            #pragma unroll
            for (int i = 0; i < 16; i++) m[q][i] = mul2_(m[q][i], sg2);
        }
    }

    u64 cp = 0ull;
    if (!lastLayer){
        // coors MLP -> per-edge scalar weight; 2 c1 rows per iteration for ILP
        float c2b0 = c2b[0];
        float cw[4] = {c2b0, c2b0, c2b0, c2b0};
        #pragma unroll 1
        for (int vp = 0; vp < KK/2; vp++){
            const ulonglong2* ccA = (const ulonglong2*)(sC1t + (2*vp)*36);
            const ulonglong2* ccB = (const ulonglong2*)(sC1t + (2*vp+1)*36);
            u64 sa[4] = {0ull,0ull,0ull,0ull};
            u64 sb[4] = {0ull,0ull,0ull,0ull};
            #pragma unroll
            for (int k = 0; k < 8; k++){
                ulonglong2 wa = ccA[k], wb = ccB[k];
                #pragma unroll
                for (int q = 0; q < 4; q++){
                    sa[q] = fma2_(m[q][2*k],   wa.x, sa[q]);
                    sa[q] = fma2_(m[q][2*k+1], wa.y, sa[q]);
                    sb[q] = fma2_(m[q][2*k],   wb.x, sb[q]);
                    sb[q] = fma2_(m[q][2*k+1], wb.y, sb[q]);
                }
            }
            float2 cb2 = ((const float2*)sC1b)[vp];
            float2 c22 = ((const float2*)sC2)[vp];
            #pragma unroll
            for (int q = 0; q < 4; q++){
                float2 fa = upk2(sa[q]), fb = upk2(sb[q]);
                cw[q] += lrelu(cb2.x + fa.x + fa.y)*c22.x;
                cw[q] += lrelu(cb2.y + fb.x + fb.y)*c22.y;
            }
        }

        // coordinate contributions
        const float2* Cg = (const float2*)(g_coors[cur]);
        float2 ci = Cg[gi];
        float sscl = scl[0];
        float cx = 0.f, cy = 0.f;
        #pragma unroll
        for (int q = 0; q < 4; q++){
            float2 cj = Cg[b*NN + j[q]];
            float rx = ci.x - cj.x, ry = ci.y - cj.y;
            float nm = fmaxf(sqrtf(rx*rx + ry*ry), 1e-8f);
            float ss = sscl/nm;
            cx += cw[q]*(rx*ss);
            cy += cw[q]*(ry*ss);
        }
        cp = pk2(cx, cy);
    }

    // warp-level reduction (node fully inside this warp)
    u64 mt[16];
    #pragma unroll
    for (int i = 0; i < 16; i++)
        mt[i] = add2_(add2_(m[0][i], m[1][i]), add2_(m[2][i], m[3][i]));
    #pragma unroll
    for (int off = 16; off > 0; off >>= 1){
        #pragma unroll
        for (int i = 0; i < 16; i++)
            mt[i] = add2_(mt[i], __shfl_xor_sync(0xffffffffu, mt[i], off));
        cp = add2_(cp, __shfl_xor_sync(0xffffffffu, cp, off));
    }
    if (lane < 16)
        ((u64*)(g_msum + (size_t)gi*DD))[lane] = mt[lane];
    if (!lastLayer && lane == 0){
        float2 cf = upk2(cp);
        float2 ci = ((const float2*)(g_coors[cur]))[gi];
        ((float2*)g_coors[cur^1])[gi] = make_float2(ci.x + cf.x, ci.y + cf.y);
    }
}

extern "C" void kernel_launch(void* const* d_in, const int* in_sizes, int n_in,
                              void* d_out, int out_size){
    const float* feat = (const float*)d_in[0];
    const float* coor = (const float*)d_in[1];
    // d_in[2] = batch (equal-size graphs; unused)
    const float* ew  = (const float*)d_in[3];
    const float* eb  = (const float*)d_in[4];
    const float* e1w = (const float*)d_in[5];
    const float* e1b = (const float*)d_in[6];
    const float* e2w = (const float*)d_in[7];
    const float* e2b = (const float*)d_in[8];
    const float* gw  = (const float*)d_in[9];
    const float* gb  = (const float*)d_in[10];
    const float* c1w = (const float*)d_in[11];
    const float* c1b = (const float*)d_in[12];
    const float* c2w = (const float*)d_in[13];
    const float* c2b = (const float*)d_in[14];
    const float* n1w = (const float*)d_in[15];
    const float* n1b = (const float*)d_in[16];
    const float* n2w = (const float*)d_in[17];
    const float* n2b = (const float*)d_in[18];
    const float* scl = (const float*)d_in[19];

    cudaMemcpyToSymbolAsync(g_coors, coor, BN*2*sizeof(float), 0,
                            cudaMemcpyDeviceToDevice, 0);

    // layer 0: knn(0) fused with embed+pre(0)
    embed_knn_kernel<<<BN + BN/2, 256>>>(0, feat, ew, eb, e1w, e1b);
    edge_kernel<<<BN/4, 128>>>(0, 0,
                             e1w, e2w, e2b, gw, gb, c1w, c1b, c2w, c2b, scl);

    // boundaries: node_pre(l) fused with knn(l+1)
    for (int l = 1; l < 3; l++){
        int npCur = (l-1) & 1;         // buffer the previous layer computed into
        int knnCur = l & 1;            // coords written by previous edge
        node_knn_kernel<<<BN + BN/2, 256>>>(npCur, knnCur,
                                  n1w + (l-1)*64*64, n1b + (l-1)*64,
                                  n2w + (l-1)*64*DD, n2b + (l-1)*DD,
                                  e1w + l*65*EH, e1b + l*EH);
        edge_kernel<<<BN/4, 128>>>(knnCur, l == 2,
                                 e1w + l*65*EH, e2w + l*EH*DD, e2b + l*DD,
                                 gw + l*DD, gb + l,
                                 c1w + l*DD*KK, c1b + l*KK,
                                 c2w + l*KK, c2b + l, scl + l);
    }

    // final node MLP -> d_out
    node_last_kernel<<<BN/2, 256>>>(0, (float*)d_out,
                              n1w + 2*64*64, n1b + 2*64,
                              n2w + 2*64*DD, n2b + 2*DD);
}